// round 3
// baseline (speedup 1.0000x reference)
#include <cuda_runtime.h>

// LocSE fused kernel for GB300.
// Shapes (fixed): B=4, N=16384, DIMS=2, K1=17, UNITS=128, CH=53.
// Key algebraic identity: the (17 x 53) @ (53 x 64) per-neighborhood matmul
// factorizes into one shared 34-dim projection S[u] plus a rank-3 per-j term.

#define NPTS   16384
#define BN     65536          // B*N
#define K1V    17
#define WARPS  8
#define OUT_FLOATS_PER_G 2176 // 17*128

__global__ __launch_bounds__(256, 4)
void locse_kernel(const float2* __restrict__ pc,      // (B,N) float2
                  const float2* __restrict__ feats,   // (B,N,32) float2 (64 floats)
                  const int*    __restrict__ nidx,    // (B,N,17)
                  const float*  __restrict__ W,       // (53,64)
                  const float*  __restrict__ bvec,    // (64,)
                  float*        __restrict__ out,     // (B,N,17,128)
                  float*        __restrict__ ggf)     // (B,N,1,2)
{
    // S-projection weights, interleaved: sWs2[(2i+d)*32 + lane] holds
    // ( W[2+3i+d][2*lane], W[2+3i+d][2*lane+1] )
    __shared__ float2 sWs2[34 * 32];
    __shared__ float  sWx[64], sWy[64], sWn[64], sB[64];
    __shared__ float4 pts[WARPS][K1V];   // (x, y, norm, idx_as_float)

    const int tid = threadIdx.x;

    // ---- stage derived weights (once per block) ----
    if (tid < 64) {
        const int u = tid;
        float wx = W[u];          // W[0][u]
        float wy = W[64 + u];     // W[1][u]
        float wn = 0.f;
        #pragma unroll
        for (int i = 0; i < K1V; i++) {
            wx -= W[(2 + 3 * i) * 64 + u];
            wy -= W[(3 + 3 * i) * 64 + u];
            wn += W[(4 + 3 * i) * 64 + u];
        }
        sWx[u] = wx; sWy[u] = wy; sWn[u] = wn; sB[u] = bvec[u];
    }
    {
        float* sWsF = (float*)sWs2;
        for (int t = tid; t < 34 * 64; t += 256) {
            const int c = t >> 6, u = t & 63;
            const int i = c >> 1, d = c & 1;
            sWsF[t] = W[(2 + 3 * i + d) * 64 + u];
        }
    }
    __syncthreads();

    const int lane = tid & 31, warp = tid >> 5;
    const unsigned g = blockIdx.x * WARPS + warp;   // neighborhood id in [0, BN)
    if (g >= BN) return;
    const unsigned b = g >> 14;                     // g / 16384
    const int* __restrict__ ip = nidx + (size_t)g * K1V;

    // ---- phase A: gather 17 points, norms ----
    float x = 0.f, y = 0.f;
    if (lane < K1V) {
        const int ii = ip[lane];
        const float2 p = pc[(size_t)b * NPTS + ii];
        x = p.x; y = p.y;
        const float nrm = sqrtf(x * x + y * y);
        pts[warp][lane] = make_float4(x, y, nrm, __int_as_float(ii));
    }
    __syncwarp();

    // ---- ggf: two-pass centered stats over 17 points (matches reference) ----
    float sx = x, sy = y;
    #pragma unroll
    for (int o = 16; o; o >>= 1) {
        sx += __shfl_xor_sync(0xffffffffu, sx, o);
        sy += __shfl_xor_sync(0xffffffffu, sy, o);
    }
    const float inv17 = 1.0f / 17.0f;
    const float mx = sx * inv17, my = sy * inv17;
    const float xc = (lane < K1V) ? (x - mx) : 0.f;
    const float yc = (lane < K1V) ? (y - my) : 0.f;
    float sxx = xc * xc, syy = yc * yc, sxy = xc * yc;
    #pragma unroll
    for (int o = 16; o; o >>= 1) {
        sxx += __shfl_xor_sync(0xffffffffu, sxx, o);
        syy += __shfl_xor_sync(0xffffffffu, syy, o);
        sxy += __shfl_xor_sync(0xffffffffu, sxy, o);
    }
    if (lane == 0) {
        const float vx = sxx * inv17, vy = syy * inv17, cov = sxy * inv17;
        const float m    = cov / (vx + 1e-8f);
        const float pear = cov / (sqrtf(vx * vy) + 1e-8f);
        ggf[(size_t)g * 2]     = m;
        ggf[(size_t)g * 2 + 1] = 1.0f - pear;
    }

    // ---- phase B: shared projection S[u] (each lane owns u0=2*lane, u1=2*lane+1) ----
    float acc0 = sB[2 * lane], acc1 = sB[2 * lane + 1];
    #pragma unroll
    for (int i = 0; i < K1V; i++) {
        const float4 pt  = pts[warp][i];                 // LDS broadcast
        const float2 wxv = sWs2[(2 * i) * 32 + lane];
        const float2 wyv = sWs2[(2 * i + 1) * 32 + lane];
        acc0 = fmaf(pt.x, wxv.x, acc0);
        acc1 = fmaf(pt.x, wxv.y, acc1);
        acc0 = fmaf(pt.y, wyv.x, acc0);
        acc1 = fmaf(pt.y, wyv.y, acc1);
    }
    const float wx0 = sWx[2 * lane], wx1 = sWx[2 * lane + 1];
    const float wy0 = sWy[2 * lane], wy1 = sWy[2 * lane + 1];
    const float wn0 = sWn[2 * lane], wn1 = sWn[2 * lane + 1];

    // ---- phase C: per-j rank-3 term + relu, feats gather, coalesced stores ----
    float2* __restrict__ outBase = (float2*)out + (size_t)g * (OUT_FLOATS_PER_G / 2);
    const float2* __restrict__ fb = feats + (size_t)b * NPTS * 32;

    #pragma unroll
    for (int j = 0; j < K1V; j++) {
        const float4 pt = pts[warp][j];
        const int ii = __float_as_int(pt.w);
        const float2 f = fb[(size_t)ii * 32 + lane];

        float r0 = fmaf(pt.x, wx0, acc0);
        r0 = fmaf(pt.y, wy0, r0);
        r0 = fmaf(pt.z, wn0, r0);
        r0 = fmaxf(r0, 0.f);
        float r1 = fmaf(pt.x, wx1, acc1);
        r1 = fmaf(pt.y, wy1, r1);
        r1 = fmaf(pt.z, wn1, r1);
        r1 = fmaxf(r1, 0.f);

        float2* row = outBase + j * 64;
        __stcs(row + lane, f);                      // channels [0,64): n_feats
        __stcs(row + 32 + lane, make_float2(r0, r1)); // channels [64,128): relu MLP
    }
}

extern "C" void kernel_launch(void* const* d_in, const int* in_sizes, int n_in,
                              void* d_out, int out_size) {
    const float2* pc    = (const float2*)d_in[0];
    const float2* feats = (const float2*)d_in[1];
    const int*    nidx  = (const int*)d_in[2];
    const float*  W     = (const float*)d_in[3];
    const float*  bvec  = (const float*)d_in[4];

    float* out = (float*)d_out;
    // ggf tensor is concatenated after the main output
    float* ggf = out + (size_t)BN * OUT_FLOATS_PER_G;

    locse_kernel<<<BN / WARPS, 256>>>(pc, feats, nidx, W, bvec, out, ggf);
}

// round 5
// speedup vs baseline: 1.3369x; 1.3369x over previous
#include <cuda_runtime.h>

// LocSE fused kernel for GB300.
// Shapes (fixed): B=4, N=16384, DIMS=2, K1=17, UNITS=128, CH=53.
// Factorization: the (17 x 53) @ (53 x 64) per-neighborhood matmul
// = one shared 34-dim projection S[u] + a rank-3 per-j term.
// R4: occupancy-focused — launch_bounds(256,6) (target <=42 regs),
// software-pipelined phase C (unroll 1 + 1-deep prefetch) to cut live regs.

#define NPTS   16384
#define BN     65536          // B*N
#define K1V    17
#define WARPS  8
#define OUT_FLOATS_PER_G 2176 // 17*128

__global__ __launch_bounds__(256, 6)
void locse_kernel(const float2* __restrict__ pc,      // (B,N) float2
                  const float2* __restrict__ feats,   // (B,N,32) float2 (64 floats)
                  const int*    __restrict__ nidx,    // (B,N,17)
                  const float*  __restrict__ W,       // (53,64)
                  const float*  __restrict__ bvec,    // (64,)
                  float*        __restrict__ out,     // (B,N,17,128)
                  float2*       __restrict__ ggf)     // (B,N,1,2) as float2
{
    // S-projection weights, interleaved: sWs2[(2i+d)*32 + lane] holds
    // ( W[2+3i+d][2*lane], W[2+3i+d][2*lane+1] )
    __shared__ float2 sWs2[34 * 32];
    __shared__ float  sWx[64], sWy[64], sWn[64], sB[64];
    __shared__ float4 pts[WARPS][K1V];   // (x, y, norm, idx_as_float)

    const int tid = threadIdx.x;

    // ---- stage derived weights (once per block) ----
    if (tid < 64) {
        const int u = tid;
        float wx = W[u];          // W[0][u]
        float wy = W[64 + u];     // W[1][u]
        float wn = 0.f;
        #pragma unroll
        for (int i = 0; i < K1V; i++) {
            wx -= W[(2 + 3 * i) * 64 + u];
            wy -= W[(3 + 3 * i) * 64 + u];
            wn += W[(4 + 3 * i) * 64 + u];
        }
        sWx[u] = wx; sWy[u] = wy; sWn[u] = wn; sB[u] = bvec[u];
    }
    {
        float* sWsF = (float*)sWs2;
        #pragma unroll 1
        for (int t = tid; t < 34 * 64; t += 256) {
            const int c = t >> 6, u = t & 63;
            const int i = c >> 1, d = c & 1;
            sWsF[t] = W[(2 + 3 * i + d) * 64 + u];
        }
    }
    __syncthreads();

    const int lane = tid & 31, warp = tid >> 5;
    const unsigned g = blockIdx.x * WARPS + warp;   // neighborhood id in [0, BN)
    const unsigned b = g >> 14;                     // g / 16384
    const int* __restrict__ ip = nidx + (size_t)g * K1V;

    // ---- phase A: gather 17 points, norms ----
    float x = 0.f, y = 0.f;
    if (lane < K1V) {
        const int ii = ip[lane];
        const float2 p = pc[(size_t)b * NPTS + ii];
        x = p.x; y = p.y;
        const float nrm = sqrtf(x * x + y * y);
        pts[warp][lane] = make_float4(x, y, nrm, __int_as_float(ii));
    }
    __syncwarp();

    // ---- ggf: two-pass centered stats over 17 points (matches reference) ----
    float sx = x, sy = y;
    #pragma unroll
    for (int o = 16; o; o >>= 1) {
        sx += __shfl_xor_sync(0xffffffffu, sx, o);
        sy += __shfl_xor_sync(0xffffffffu, sy, o);
    }
    const float inv17 = 1.0f / 17.0f;
    const float mx = sx * inv17, my = sy * inv17;
    const float xc = (lane < K1V) ? (x - mx) : 0.f;
    const float yc = (lane < K1V) ? (y - my) : 0.f;
    float sxx = xc * xc, syy = yc * yc, sxy = xc * yc;
    #pragma unroll
    for (int o = 16; o; o >>= 1) {
        sxx += __shfl_xor_sync(0xffffffffu, sxx, o);
        syy += __shfl_xor_sync(0xffffffffu, syy, o);
        sxy += __shfl_xor_sync(0xffffffffu, sxy, o);
    }
    if (lane == 0) {
        const float vx = sxx * inv17, vy = syy * inv17, cov = sxy * inv17;
        const float m    = cov / (vx + 1e-8f);
        const float pear = cov / (sqrtf(vx * vy) + 1e-8f);
        __stcs(ggf + g, make_float2(m, 1.0f - pear));
    }

    // ---- phase B: shared projection S[u] (each lane owns u0=2*lane, u1=2*lane+1) ----
    float acc0 = sB[2 * lane], acc1 = sB[2 * lane + 1];
    #pragma unroll
    for (int i = 0; i < K1V; i++) {
        const float4 pt  = pts[warp][i];                 // LDS broadcast
        const float2 wxv = sWs2[(2 * i) * 32 + lane];
        const float2 wyv = sWs2[(2 * i + 1) * 32 + lane];
        acc0 = fmaf(pt.x, wxv.x, acc0);
        acc1 = fmaf(pt.x, wxv.y, acc1);
        acc0 = fmaf(pt.y, wyv.x, acc0);
        acc1 = fmaf(pt.y, wyv.y, acc1);
    }
    const float wx0 = sWx[2 * lane], wx1 = sWx[2 * lane + 1];
    const float wy0 = sWy[2 * lane], wy1 = sWy[2 * lane + 1];
    const float wn0 = sWn[2 * lane], wn1 = sWn[2 * lane + 1];

    // ---- phase C: per-j rank-3 term + relu, feats gather, coalesced stores ----
    // Software-pipelined (1-deep prefetch) to keep live registers low and let
    // higher occupancy supply the memory-level parallelism.
    float2* __restrict__ outBase = (float2*)out + (size_t)g * (OUT_FLOATS_PER_G / 2);
    const float2* __restrict__ fb = feats + (size_t)b * NPTS * 32;

    float4 pt = pts[warp][0];
    float2 f  = fb[(size_t)__float_as_int(pt.w) * 32 + lane];

    #pragma unroll 1
    for (int j = 0; j < K1V; j++) {
        float4 ptn;
        float2 fn;
        if (j + 1 < K1V) {
            ptn = pts[warp][j + 1];
            fn  = fb[(size_t)__float_as_int(ptn.w) * 32 + lane];
        }

        float r0 = fmaf(pt.x, wx0, acc0);
        r0 = fmaf(pt.y, wy0, r0);
        r0 = fmaf(pt.z, wn0, r0);
        r0 = fmaxf(r0, 0.f);
        float r1 = fmaf(pt.x, wx1, acc1);
        r1 = fmaf(pt.y, wy1, r1);
        r1 = fmaf(pt.z, wn1, r1);
        r1 = fmaxf(r1, 0.f);

        float2* row = outBase + j * 64;
        __stcs(row + lane, f);                        // channels [0,64): n_feats
        __stcs(row + 32 + lane, make_float2(r0, r1)); // channels [64,128): relu MLP

        pt = ptn;
        f  = fn;
    }
}

extern "C" void kernel_launch(void* const* d_in, const int* in_sizes, int n_in,
                              void* d_out, int out_size) {
    const float2* pc    = (const float2*)d_in[0];
    const float2* feats = (const float2*)d_in[1];
    const int*    nidx  = (const int*)d_in[2];
    const float*  W     = (const float*)d_in[3];
    const float*  bvec  = (const float*)d_in[4];

    float* out = (float*)d_out;
    // ggf tensor is concatenated after the main output
    float2* ggf = (float2*)(out + (size_t)BN * OUT_FLOATS_PER_G);

    locse_kernel<<<BN / WARPS, 256>>>(pc, feats, nidx, W, bvec, out, ggf);
}